// round 9
// baseline (speedup 1.0000x reference)
#include <cuda_runtime.h>
#include <cuda_bf16.h>

// Problem dims
#define BATCH  64
#define SDIM   4096
#define DDIM   256
#define SCHUNK 128                       // rows per CTA
#define NCHUNK (SDIM / SCHUNK)           // 32
#define NBLK   (BATCH * NCHUNK)          // 2048 small CTAs

// Scratch for cross-CTA partials (no allocation allowed -> device globals)
__device__ float g_acc[NBLK * DDIM];     // 2 MB
__device__ float g_sum[NBLK];
__device__ int   g_cnt[BATCH];           // zero-init; re-armed by finalizer each run

__device__ __forceinline__ float warp_sum(float v) {
    #pragma unroll
    for (int o = 16; o; o >>= 1) v += __shfl_xor_sync(0xffffffffu, v, o);
    return v;
}

// exp(tanh(x)) with a short chain: tanh(x) = 1 - 2/(e^{2x}+1).
// Saturates correctly: x>>0 -> e^{2x}=inf -> th=1;  x<<0 -> th=-1.
__device__ __forceinline__ float exp_tanh(float x) {
    const float t  = __expf(2.f * x);
    const float th = 1.f - __fdividef(2.f, t + 1.f);
    return __expf(th);
}

// ---------------------------------------------------------------------------
// Single pass over memory (268 MB read exactly once):
//   gi = tanh(m·Wm + c_b) in [-1,1] => exp never overflows => softmax needs
//   no running max; accumulate exp(gi)*m and exp(gi) in one sweep.
// R8 lesson: the 70-74% DRAM plateau tracks warp residency (27 warps/SM at
// the 256-thread/occ-4 cap), not the load scheme. This version: 128-thread
// CTAs at occ 10 -> ~40 warps/SM, plain LDG.128 warp-per-row, short
// activation chain. Last CTA per batch finalizes (threadfence pattern).
// ---------------------------------------------------------------------------
__global__ __launch_bounds__(128, 10)
void att_fused(const float* __restrict__ memory,
               const float* __restrict__ aspect,
               const float* __restrict__ W,
               const float* __restrict__ bias,
               float* __restrict__ out)
{
    __shared__ float sacc[DDIM];
    __shared__ float ssum;
    __shared__ float sc;
    __shared__ int   s_old;

    const int tid  = threadIdx.x;        // 0..127
    const int lane = tid & 31;
    const int warp = tid >> 5;           // 0..3
    const int blk  = blockIdx.x;
    const int b    = blk >> 5;           // / NCHUNK
    const int chnk = blk & (NCHUNK - 1);

    // ---- c_b = aspect[b]·Wa + bias (128 threads cover 256 dims in 2) ----
    {
        float v = aspect[b * DDIM + tid]       * W[DDIM + tid]
                + aspect[b * DDIM + 128 + tid] * W[DDIM + 128 + tid];
        v = warp_sum(v);
        if (tid == 0) { ssum = 0.f; sc = bias[0]; }
        sacc[tid] = 0.f; sacc[128 + tid] = 0.f;
        __syncthreads();
        if (lane == 0) atomicAdd(&sc, v);
        __syncthreads();
    }
    const float cb = sc;

    // ---- Wm slice in registers: lane covers d = 4*lane.. and 128+4*lane.. ----
    const float4 wm0 = *reinterpret_cast<const float4*>(W + 4 * lane);
    const float4 wm1 = *reinterpret_cast<const float4*>(W + 128 + 4 * lane);

    float4 a0 = make_float4(0.f, 0.f, 0.f, 0.f);
    float4 a1 = make_float4(0.f, 0.f, 0.f, 0.f);
    float  sw = 0.f;

    const float4* base = reinterpret_cast<const float4*>(
        memory + ((long)b * SDIM + (long)chnk * SCHUNK) * DDIM);

    // warp-per-row: rows r = warp + 4*i, i = 0..31; unroll 2 -> two
    // independent load/reduce/activation chains in flight per warp
    #pragma unroll 2
    for (int i = 0; i < 32; i++) {
        const float4* row = base + (long)(warp + 4 * i) * 64;
        const float4 m0 = row[lane];
        const float4 m1 = row[32 + lane];

        float d = m0.x * wm0.x + m0.y * wm0.y + m0.z * wm0.z + m0.w * wm0.w
                + m1.x * wm1.x + m1.y * wm1.y + m1.z * wm1.z + m1.w * wm1.w;
        d = warp_sum(d);
        const float w = exp_tanh(d + cb);

        a0.x += w * m0.x; a0.y += w * m0.y; a0.z += w * m0.z; a0.w += w * m0.w;
        a1.x += w * m1.x; a1.y += w * m1.y; a1.z += w * m1.z; a1.w += w * m1.w;
        sw   += w;                        // uniform across lanes post-butterfly
    }

    // ---- combine 4 warps via smem atomics (spread addresses, cheap) ----
    atomicAdd(&sacc[4 * lane + 0], a0.x);
    atomicAdd(&sacc[4 * lane + 1], a0.y);
    atomicAdd(&sacc[4 * lane + 2], a0.z);
    atomicAdd(&sacc[4 * lane + 3], a0.w);
    atomicAdd(&sacc[128 + 4 * lane + 0], a1.x);
    atomicAdd(&sacc[128 + 4 * lane + 1], a1.y);
    atomicAdd(&sacc[128 + 4 * lane + 2], a1.z);
    atomicAdd(&sacc[128 + 4 * lane + 3], a1.w);
    if (lane == 0) atomicAdd(&ssum, sw);
    __syncthreads();

    g_acc[blk * DDIM + tid]       = sacc[tid];
    g_acc[blk * DDIM + 128 + tid] = sacc[128 + tid];
    if (tid == 0) g_sum[blk] = ssum;
    __syncthreads();

    // ---- last-CTA-per-batch finalize ----
    if (tid == 0) {
        __threadfence();
        s_old = atomicAdd(&g_cnt[b], 1);
    }
    __syncthreads();
    if (s_old == NCHUNK - 1) {
        __threadfence();                 // acquire siblings' partials
        float acc0 = 0.f, acc1 = 0.f, s = 0.f;
        #pragma unroll 4
        for (int c = 0; c < NCHUNK; c++) {
            const float* p = &g_acc[(b * NCHUNK + c) * DDIM];
            acc0 += p[tid];
            acc1 += p[128 + tid];
            s    += g_sum[b * NCHUNK + c];
        }
        const float inv = __fdividef(1.f, s);
        out[b * DDIM + tid]       = acc0 * inv;
        out[b * DDIM + 128 + tid] = acc1 * inv;
        __syncthreads();
        if (tid == 0) g_cnt[b] = 0;      // re-arm for next graph replay
    }
}

extern "C" void kernel_launch(void* const* d_in, const int* in_sizes, int n_in,
                              void* d_out, int out_size)
{
    // Map inputs by element count:
    //   memory: B*S*D = 67108864, aspect: B*D = 16384, W: 2*D = 512, b: 1
    const float *aspect = nullptr, *memory = nullptr, *W = nullptr, *bias = nullptr;
    for (int i = 0; i < n_in; i++) {
        const long n = (long)in_sizes[i];
        const float* p = (const float*)d_in[i];
        if      (n == (long)BATCH * SDIM * DDIM) memory = p;
        else if (n == (long)BATCH * DDIM)        aspect = p;
        else if (n == 2 * DDIM)                  W      = p;
        else if (n == 1)                         bias   = p;
    }

    att_fused<<<NBLK, 128>>>(memory, aspect, W, bias, (float*)d_out);
}

// round 10
// speedup vs baseline: 1.2838x; 1.2838x over previous
#include <cuda_runtime.h>
#include <cuda_bf16.h>

// Problem dims
#define BATCH  64
#define SDIM   4096
#define DDIM   256
#define NCHUNK 9                          // chunks per batch
#define NBLK   (BATCH * NCHUNK)           // 576 CTAs = single wave, 4/SM on 132 SMs
#define STAGES 5                          // per-lane cp.async ring depth

// Scratch for cross-CTA partials (no allocation allowed -> device globals)
__device__ float g_acc[NBLK * DDIM];
__device__ float g_sum[NBLK];
__device__ int   g_cnt[BATCH];            // zero-init; re-armed by finalizer

__device__ __forceinline__ float warp_sum(float v) {
    #pragma unroll
    for (int o = 16; o; o >>= 1) v += __shfl_xor_sync(0xffffffffu, v, o);
    return v;
}

// exp(tanh(x)) via tanh(x) = 1 - 2/(e^{2x}+1); saturates correctly at +-1.
// Measured rel_err 1.01e-6 in R9 (same as tanhf path).
__device__ __forceinline__ float exp_tanh(float x) {
    const float t  = __expf(2.f * x);
    const float th = 1.f - __fdividef(2.f, t + 1.f);
    return __expf(th);
}

__device__ __forceinline__ void cp_async16(void* smem, const void* gmem) {
    unsigned sa = (unsigned)__cvta_generic_to_shared(smem);
    asm volatile("cp.async.cg.shared.global [%0], [%1], 16;" :: "r"(sa), "l"(gmem));
}
__device__ __forceinline__ void cp_commit() {
    asm volatile("cp.async.commit_group;");
}
template<int N> __device__ __forceinline__ void cp_wait() {
    asm volatile("cp.async.wait_group %0;" :: "n"(N));
}

// ---------------------------------------------------------------------------
// Single pass over memory (268 MB read exactly once):
//   gi = tanh(m·Wm + c_b) in [-1,1] => exp never overflows => softmax needs
//   no running max; accumulate exp(gi)*m and exp(gi) in one sweep.
//
// Hot loop is a LANE-PRIVATE cp.async pipeline: lane j stages exactly the two
// float4s it later reads (ring[warp][s][j], [32+j]), so wait_group alone
// gives visibility — no warp/CTA sync in the loop, 4 rows/warp permanently
// in flight, registers stay ~45.
// Grid 576 = 64 x 9: all CTAs resident (occ 4), SM load max/mean = 1.028.
// Last CTA per batch finalizes (threadfence-reduction pattern).
// ---------------------------------------------------------------------------
__global__ __launch_bounds__(256, 4)
void att_fused(const float* __restrict__ memory,
               const float* __restrict__ aspect,
               const float* __restrict__ W,
               const float* __restrict__ bias,
               float* __restrict__ out)
{
    __shared__ __align__(16) float4 ring[8][STAGES][64];  // 40 KB staging
    __shared__ float wred[8];
    __shared__ float wsum[8];
    __shared__ float sc;
    __shared__ int   s_old;

    const int tid  = threadIdx.x;
    const int lane = tid & 31;
    const int warp = tid >> 5;
    const int blk  = blockIdx.x;
    const int b    = blk / NCHUNK;
    const int chnk = blk - b * NCHUNK;

    // chunk row range within the batch: chunk0 = 456 rows, others 455
    const int rbase = chnk ? (456 + 455 * (chnk - 1)) : 0;
    const int nrows = chnk ? 455 : 456;

    // ---- c_b = aspect[b]·Wa + bias (deterministic combine) ----
    {
        float v = warp_sum(aspect[b * DDIM + tid] * W[DDIM + tid]);
        if (lane == 0) wred[warp] = v;
        __syncthreads();
        if (tid == 0) {
            float c = bias[0];
            #pragma unroll
            for (int w = 0; w < 8; w++) c += wred[w];
            sc = c;
        }
        __syncthreads();
    }
    const float cb = sc;

    // ---- Wm slice in registers: lane covers d = 4*lane.. and 128+4*lane.. ----
    const float4 wm0 = *reinterpret_cast<const float4*>(W + 4 * lane);
    const float4 wm1 = *reinterpret_cast<const float4*>(W + 128 + 4 * lane);

    // this warp's rows: global rows rbase+warp+8*i, i = 0..N-1 (N = 56 or 57)
    const int N = (nrows - warp + 7) >> 3;
    const float4* base4 = reinterpret_cast<const float4*>(
        memory + ((long)b * SDIM + rbase + warp) * DDIM);

    auto issue = [&](int i) {
        const float4* g = base4 + (long)i * 512;          // 8 rows * 64 float4
        float4* s = &ring[warp][i % STAGES][0];
        cp_async16(&s[lane],      g + lane);
        cp_async16(&s[32 + lane], g + 32 + lane);
        cp_commit();
    };

    // prologue: rows 0..3 in flight (every warp has >= 56 rows)
    issue(0); issue(1); issue(2); issue(3);

    float4 a0 = make_float4(0.f, 0.f, 0.f, 0.f);
    float4 a1 = make_float4(0.f, 0.f, 0.f, 0.f);
    float  sw = 0.f;

    for (int i = 0; i < N; i++) {
        if (i + 4 < N) issue(i + 4);
        // ledger: committed = min(N, i+5); need pending <= min(4, N-1-i)
        if (N - 1 - i >= 4) cp_wait<4>();
        else                cp_wait<0>();                  // tail drain

        const int s = i % STAGES;
        const float4 m0 = ring[warp][s][lane];             // own writes only
        const float4 m1 = ring[warp][s][32 + lane];

        float d = m0.x * wm0.x + m0.y * wm0.y + m0.z * wm0.z + m0.w * wm0.w
                + m1.x * wm1.x + m1.y * wm1.y + m1.z * wm1.z + m1.w * wm1.w;
        d = warp_sum(d);
        const float w = exp_tanh(d + cb);

        a0.x += w * m0.x; a0.y += w * m0.y; a0.z += w * m0.z; a0.w += w * m0.w;
        a1.x += w * m1.x; a1.y += w * m1.y; a1.z += w * m1.z; a1.w += w * m1.w;
        sw   += w;                          // uniform across lanes post-butterfly
    }

    // ---- deterministic 8-warp combine; slab overlays the now-dead ring ----
    __syncthreads();                        // all warps done with ring
    float* slab = reinterpret_cast<float*>(ring);          // [8][DDIM]
    float* my   = slab + warp * DDIM;
    my[4 * lane + 0] = a0.x;  my[4 * lane + 1] = a0.y;
    my[4 * lane + 2] = a0.z;  my[4 * lane + 3] = a0.w;
    my[128 + 4 * lane + 0] = a1.x;  my[128 + 4 * lane + 1] = a1.y;
    my[128 + 4 * lane + 2] = a1.z;  my[128 + 4 * lane + 3] = a1.w;
    if (lane == 0) wsum[warp] = sw;
    __syncthreads();

    {
        float t = 0.f;
        #pragma unroll
        for (int w = 0; w < 8; w++) t += slab[w * DDIM + tid];
        g_acc[blk * DDIM + tid] = t;
        if (tid == 0) {
            float s = 0.f;
            #pragma unroll
            for (int w = 0; w < 8; w++) s += wsum[w];
            g_sum[blk] = s;
        }
    }
    __syncthreads();

    // ---- last-CTA-per-batch finalize ----
    if (tid == 0) {
        __threadfence();
        s_old = atomicAdd(&g_cnt[b], 1);
    }
    __syncthreads();
    if (s_old == NCHUNK - 1) {
        __threadfence();                    // acquire siblings' partials
        float acc = 0.f, s = 0.f;
        #pragma unroll
        for (int c = 0; c < NCHUNK; c++) {
            acc += g_acc[(b * NCHUNK + c) * DDIM + tid];
            s   += g_sum[b * NCHUNK + c];
        }
        out[b * DDIM + tid] = acc / s;
        __syncthreads();
        if (tid == 0) g_cnt[b] = 0;         // re-arm for next graph replay
    }
}

extern "C" void kernel_launch(void* const* d_in, const int* in_sizes, int n_in,
                              void* d_out, int out_size)
{
    // Map inputs by element count:
    //   memory: B*S*D = 67108864, aspect: B*D = 16384, W: 2*D = 512, b: 1
    const float *aspect = nullptr, *memory = nullptr, *W = nullptr, *bias = nullptr;
    for (int i = 0; i < n_in; i++) {
        const long n = (long)in_sizes[i];
        const float* p = (const float*)d_in[i];
        if      (n == (long)BATCH * SDIM * DDIM) memory = p;
        else if (n == (long)BATCH * DDIM)        aspect = p;
        else if (n == 2 * DDIM)                  W      = p;
        else if (n == 1)                         bias   = p;
    }

    att_fused<<<NBLK, 256>>>(memory, aspect, W, bias, (float*)d_out);
}